// round 12
// baseline (speedup 1.0000x reference)
#include <cuda_runtime.h>
#include <cstdint>

#define S_LEN 512
#define B_SZ  64
#define HIDD  1024
#define EMBD  512
#define NCLS  32000
#define FEATD 2048
#define RNN_NCTA 128
// Wsh [1024k][32j] = 128KB ; hd dup [1024k][8b pairs] = 64KB ; scratch 16KB
#define RNN_SMEM (1024 * 32 * 4 + 1024 * 16 * 4 + 16384)

#define FFMA2(d, a, b) asm("fma.rn.f32x2 %0, %1, %2, %0;" : "+l"(d) : "l"(a), "l"(b))
union F2U { unsigned long long u; float2 f; };

// ---- device scratch ----
__device__ float g_G[(size_t)S_LEN * B_SZ * HIDD];     // G + biases
__device__ float g_OUT[(size_t)S_LEN * B_SZ * HIDD];   // h_t
__device__ float g_scores[(S_LEN - 1) * B_SZ];
__device__ float g_attn[(S_LEN - 1) * B_SZ];
__device__ float g_attout[B_SZ * HIDD];
__device__ unsigned g_gcnt[4 * 32];            // per-group arrive counters (128B apart)
__device__ volatile unsigned g_ggen[4 * 32];   // per-group generation

__global__ void init_kernel() {
    int i = blockIdx.x * blockDim.x + threadIdx.x;
    if (i < 4 * 32) { g_gcnt[i] = 0u; *(unsigned*)&g_ggen[i] = 0u; }
}

// ---- K1: gates  G[(t*64+b)][j] = emb[X[b,t]] . W_ih[j] + b_ih[j] + b_hh[j] ----
__global__ void __launch_bounds__(256) gates_kernel(const int* __restrict__ X,
                                                    const float* __restrict__ emb,
                                                    const float* __restrict__ W_ih,
                                                    const float* __restrict__ b_ih,
                                                    const float* __restrict__ b_hh) {
    __shared__ float2 As2[16 * 64];
    __shared__ float  Bs[16 * 68];
    __shared__ int rowidx[64];
    const int n0 = blockIdx.x * 64;
    const int m0 = blockIdx.y * 64;
    const int tid = threadIdx.x;

    if (tid < 64) {
        int m = m0 + tid;
        int t = m >> 6, b = m & 63;
        rowidx[tid] = X[b * S_LEN + t];
    }
    __syncthreads();

    const int tx = tid & 15, ty = tid >> 4;
    unsigned long long acc[4][2];
#pragma unroll
    for (int i = 0; i < 4; i++) { acc[i][0] = 0ull; acc[i][1] = 0ull; }

    const int lm = tid >> 2;
    const int lk = (tid & 3) * 4;

    for (int k0 = 0; k0 < EMBD; k0 += 16) {
        float4 av = *(const float4*)&emb[(size_t)rowidx[lm] * EMBD + k0 + lk];
        As2[(lk + 0) * 64 + lm] = make_float2(av.x, av.x);
        As2[(lk + 1) * 64 + lm] = make_float2(av.y, av.y);
        As2[(lk + 2) * 64 + lm] = make_float2(av.z, av.z);
        As2[(lk + 3) * 64 + lm] = make_float2(av.w, av.w);
        float4 bv = *(const float4*)&W_ih[(size_t)(n0 + lm) * EMBD + k0 + lk];
        Bs[(lk + 0) * 68 + lm] = bv.x; Bs[(lk + 1) * 68 + lm] = bv.y;
        Bs[(lk + 2) * 68 + lm] = bv.z; Bs[(lk + 3) * 68 + lm] = bv.w;
        __syncthreads();
#pragma unroll
        for (int kk = 0; kk < 16; kk++) {
            ulonglong2 a01 = *(const ulonglong2*)&As2[kk * 64 + ty * 4];
            ulonglong2 a23 = *(const ulonglong2*)&As2[kk * 64 + ty * 4 + 2];
            ulonglong2 bp  = *(const ulonglong2*)&Bs[kk * 68 + tx * 4];
            FFMA2(acc[0][0], a01.x, bp.x); FFMA2(acc[0][1], a01.x, bp.y);
            FFMA2(acc[1][0], a01.y, bp.x); FFMA2(acc[1][1], a01.y, bp.y);
            FFMA2(acc[2][0], a23.x, bp.x); FFMA2(acc[2][1], a23.x, bp.y);
            FFMA2(acc[3][0], a23.y, bp.x); FFMA2(acc[3][1], a23.y, bp.y);
        }
        __syncthreads();
    }
    float4 bi = *(const float4*)&b_ih[n0 + tx * 4];
    float4 bh = *(const float4*)&b_hh[n0 + tx * 4];
    float bias[4] = {bi.x + bh.x, bi.y + bh.y, bi.z + bh.z, bi.w + bh.w};
#pragma unroll
    for (int i = 0; i < 4; i++) {
        int m = m0 + ty * 4 + i;
        F2U p0, p1; p0.u = acc[i][0]; p1.u = acc[i][1];
        float4 o = make_float4(p0.f.x + bias[0], p0.f.y + bias[1],
                               p1.f.x + bias[2], p1.f.y + bias[3]);
        *(float4*)&g_G[(size_t)m * HIDD + n0 + tx * 4] = o;
    }
}

// ---- group-local barrier: 32 CTAs per group ----
__device__ __forceinline__ void group_bar(unsigned target, int grp) {
    __threadfence();
    __syncthreads();
    if (threadIdx.x == 0) {
        unsigned a = atomicAdd(&g_gcnt[grp * 32], 1u);
        if (a == 31u) {
            atomicExch(&g_gcnt[grp * 32], 0u);
            __threadfence();
            atomicAdd((unsigned*)&g_ggen[grp * 32], 1u);
        } else {
            while (*(volatile unsigned*)&g_ggen[grp * 32] < target) __nanosleep(32);
        }
        __threadfence();
    }
    __syncthreads();
}

// ---- K2: persistent recurrence — 4 independent b-groups x 32 CTAs, full-K per CTA ----
// CTA c: grp = c >> 5 (16 b's), jg = c & 31 (32 j's). No split-K partials, no combine.
__global__ void __launch_bounds__(256, 1) rnn_kernel(const float* __restrict__ W_hh) {
    extern __shared__ char smem_raw[];
    float* Wsh = (float*)smem_raw;                                // [1024k][32j] undup
    float* hd  = (float*)(smem_raw + 1024 * 32 * 4);              // [1024k][8b dup pairs]
    unsigned long long* scr = (unsigned long long*)(smem_raw + 1024 * 32 * 4 + 1024 * 16 * 4);
    const int tid = threadIdx.x;
    const int c = blockIdx.x;
    const int grp = c >> 5;    // b-group: b in [grp*16, grp*16+16)
    const int jg  = c & 31;    // j-group: j in [jg*32, jg*32+32)

    // ---- load full-K W slice, k-major: Wsh[k*32 + jl] = W_hh[jg*32+jl][k] ----
    {
        int jl = tid & 31;
        int kc = (tid >> 5) * 128;
        const float* wr = &W_hh[(size_t)(jg * 32 + jl) * HIDD + kc];
#pragma unroll
        for (int q = 0; q < 32; q++) {
            float4 wv = *(const float4*)&wr[q * 4];
            Wsh[(kc + q * 4 + 0) * 32 + jl] = wv.x;
            Wsh[(kc + q * 4 + 1) * 32 + jl] = wv.y;
            Wsh[(kc + q * 4 + 2) * 32 + jl] = wv.z;
            Wsh[(kc + q * 4 + 3) * 32 + jl] = wv.w;
        }
    }
    __syncthreads();

    // compute decomposition: ks = k-eighth, r: 2 j-pairs (4 j) x 2 b
    const int ks  = tid >> 5;          // 0..7, k in [ks*128, +128)
    const int r   = tid & 31;
    const int jq  = (r & 7) * 4;       // 4 j's (2 packed pairs)
    const int blq = (r >> 3) * 2;      // 2 local b's
    // staging: thread = b-local (tid&7), 32-k chunk (tid>>3)
    const int sb  = tid & 7;
    const int skc = (tid >> 3) * 32;

    unsigned long long acc[2][2][2];   // [half][jpo][blo]

    for (int t = 0; t < S_LEN; ++t) {
#pragma unroll
        for (int half = 0; half < 2; half++) {
            // ---- stage h(t-1) for 8 b's, duplicated: hd[k*16 + 2*bl] = (h,h) ----
            if (t == 0) {
#pragma unroll
                for (int q = 0; q < 32; q++)
                    *(float2*)&hd[(skc + q) * 16 + 2 * sb] = make_float2(0.f, 0.f);
            } else {
                const float* hr = g_OUT + (size_t)(t - 1) * B_SZ * HIDD
                                + (size_t)(grp * 16 + half * 8 + sb) * HIDD + skc;
#pragma unroll
                for (int q = 0; q < 8; q++) {
                    float4 hv = __ldcg((const float4*)&hr[q * 4]);
                    int k = skc + q * 4;
                    *(float2*)&hd[(k + 0) * 16 + 2 * sb] = make_float2(hv.x, hv.x);
                    *(float2*)&hd[(k + 1) * 16 + 2 * sb] = make_float2(hv.y, hv.y);
                    *(float2*)&hd[(k + 2) * 16 + 2 * sb] = make_float2(hv.z, hv.z);
                    *(float2*)&hd[(k + 3) * 16 + 2 * sb] = make_float2(hv.w, hv.w);
                }
            }
            __syncthreads();

            // ---- compute k-eighth: acc[jp][b] packed over j-pairs ----
            unsigned long long a00 = 0ull, a10 = 0ull, a01 = 0ull, a11 = 0ull;
            const float* wb = &Wsh[jq];
            const float* hb = &hd[2 * blq];
#pragma unroll 8
            for (int k = ks * 128; k < ks * 128 + 128; k++) {
                ulonglong2 w2 = *(const ulonglong2*)&wb[k * 32];   // (wj0,wj1),(wj2,wj3)
                ulonglong2 h2 = *(const ulonglong2*)&hb[k * 16];   // dup(b0), dup(b1)
                FFMA2(a00, w2.x, h2.x);
                FFMA2(a10, w2.y, h2.x);
                FFMA2(a01, w2.x, h2.y);
                FFMA2(a11, w2.y, h2.y);
            }
            acc[half][0][0] = a00; acc[half][1][0] = a10;
            acc[half][0][1] = a01; acc[half][1][1] = a11;
            __syncthreads();   // hd reads done before restage / scratch phase
        }

        // ---- store partials to scratch: scr[(half*8+ks)*128 + jp*8 + bl] ----
        {
            const int jp0 = jq >> 1;   // 2*(r&7)
#pragma unroll
            for (int half = 0; half < 2; half++)
#pragma unroll
                for (int jpo = 0; jpo < 2; jpo++)
#pragma unroll
                    for (int blo = 0; blo < 2; blo++)
                        scr[(half * 8 + ks) * 128 + (jp0 + jpo) * 8 + (blq + blo)] =
                            acc[half][jpo][blo];
        }
        __syncthreads();

        // ---- reduce 8 k-eighths, add G, tanh, write h(t): 256 threads = 256 outputs ----
        {
            const int half = tid >> 7;
            const int idx  = tid & 127;
            const int jp   = idx & 15;
            const int bl   = idx >> 4;
            float sx = 0.f, sy = 0.f;
#pragma unroll
            for (int kq = 0; kq < 8; kq++) {
                F2U p; p.u = scr[(half * 8 + kq) * 128 + jp * 8 + bl];
                sx += p.f.x; sy += p.f.y;
            }
            int b = grp * 16 + half * 8 + bl;
            size_t gidx = (size_t)t * B_SZ * HIDD + (size_t)b * HIDD + jg * 32 + 2 * jp;
            float2 g = __ldcg((const float2*)&g_G[gidx]);
            float2 o = make_float2(tanhf(g.x + sx), tanhf(g.y + sy));
            __stcg((float2*)&g_OUT[gidx], o);
        }
        group_bar((unsigned)(t + 1), grp);
    }
}

// ---- K3a: scores ----
__global__ void __launch_bounds__(256) scores_kernel() {
    const int s = blockIdx.x;
    const int w = threadIdx.x >> 5, lane = threadIdx.x & 31;
    const float* Pv = g_OUT + (size_t)s * B_SZ * HIDD;
    const float* Lv = g_OUT + (size_t)(S_LEN - 1) * B_SZ * HIDD;
#pragma unroll
    for (int i = 0; i < 8; i++) {
        int b = w * 8 + i;
        const float* p = Pv + (size_t)b * HIDD;
        const float* l = Lv + (size_t)b * HIDD;
        float acc = 0.f;
#pragma unroll 4
        for (int k = lane; k < HIDD; k += 32) acc += p[k] * l[k];
#pragma unroll
        for (int o = 16; o > 0; o >>= 1) acc += __shfl_down_sync(0xffffffffu, acc, o);
        if (lane == 0) g_scores[s * B_SZ + b] = acc;
    }
}

// ---- K3b: softmax over s per b ----
__global__ void __launch_bounds__(512) softmax_kernel() {
    const int b = blockIdx.x;
    const int tid = threadIdx.x;
    __shared__ float red[512];
    float v = (tid < S_LEN - 1) ? g_scores[tid * B_SZ + b] : -1e30f;
    red[tid] = v;
    __syncthreads();
    for (int s = 256; s > 0; s >>= 1) {
        if (tid < s) red[tid] = fmaxf(red[tid], red[tid + s]);
        __syncthreads();
    }
    float m = red[0];
    __syncthreads();
    float e = (tid < S_LEN - 1) ? expf(v - m) : 0.f;
    red[tid] = e;
    __syncthreads();
    for (int s = 256; s > 0; s >>= 1) {
        if (tid < s) red[tid] += red[tid + s];
        __syncthreads();
    }
    float inv = 1.f / red[0];
    if (tid < S_LEN - 1) g_attn[tid * B_SZ + b] = e * inv;
}

// ---- K3c: att_out ----
__global__ void __launch_bounds__(256) attout_kernel() {
    const int b = blockIdx.y;
    const int h = blockIdx.x * 256 + threadIdx.x;
    float acc = 0.f;
#pragma unroll 4
    for (int s = 0; s < S_LEN - 1; s++)
        acc += g_attn[s * B_SZ + b] * g_OUT[(size_t)s * B_SZ * HIDD + (size_t)b * HIDD + h];
    g_attout[b * HIDD + h] = acc;
}

// ---- K4: out GEMM ----
__global__ void __launch_bounds__(256) out_gemm_kernel(const float* __restrict__ W_out,
                                                       const float* __restrict__ b_out,
                                                       float* __restrict__ out) {
    __shared__ float2 Fs2[16 * 64];
    __shared__ float  Ws[16 * 132];
    const int n0 = blockIdx.x * 128;
    const int tid = threadIdx.x;
    const int tx = tid & 31, ty = tid >> 5;
    const float* last = g_OUT + (size_t)(S_LEN - 1) * B_SZ * HIDD;

    unsigned long long acc[8][2];
#pragma unroll
    for (int i = 0; i < 8; i++) { acc[i][0] = 0ull; acc[i][1] = 0ull; }

    const int mm = tid >> 2;
    const int kq = (tid & 3) * 4;

    for (int k0 = 0; k0 < FEATD; k0 += 16) {
        int k = k0 + kq;
        const float* src = (k < HIDD) ? &g_attout[mm * HIDD + k]
                                      : &last[(size_t)mm * HIDD + (k - HIDD)];
        float4 fv = *(const float4*)src;
        Fs2[(kq + 0) * 64 + mm] = make_float2(fv.x, fv.x);
        Fs2[(kq + 1) * 64 + mm] = make_float2(fv.y, fv.y);
        Fs2[(kq + 2) * 64 + mm] = make_float2(fv.z, fv.z);
        Fs2[(kq + 3) * 64 + mm] = make_float2(fv.w, fv.w);
#pragma unroll
        for (int r = 0; r < 2; r++) {
            int f = tid + r * 256;
            int nn = f >> 2;
            int kq2 = (f & 3) * 4;
            float4 wv = *(const float4*)&W_out[(size_t)(n0 + nn) * FEATD + k0 + kq2];
            Ws[(kq2 + 0) * 132 + nn] = wv.x; Ws[(kq2 + 1) * 132 + nn] = wv.y;
            Ws[(kq2 + 2) * 132 + nn] = wv.z; Ws[(kq2 + 3) * 132 + nn] = wv.w;
        }
        __syncthreads();
#pragma unroll
        for (int kk = 0; kk < 16; kk++) {
            ulonglong2 a01 = *(const ulonglong2*)&Fs2[kk * 64 + ty * 8];
            ulonglong2 a23 = *(const ulonglong2*)&Fs2[kk * 64 + ty * 8 + 2];
            ulonglong2 a45 = *(const ulonglong2*)&Fs2[kk * 64 + ty * 8 + 4];
            ulonglong2 a67 = *(const ulonglong2*)&Fs2[kk * 64 + ty * 8 + 6];
            ulonglong2 wp  = *(const ulonglong2*)&Ws[kk * 132 + tx * 4];
            FFMA2(acc[0][0], a01.x, wp.x); FFMA2(acc[0][1], a01.x, wp.y);
            FFMA2(acc[1][0], a01.y, wp.x); FFMA2(acc[1][1], a01.y, wp.y);
            FFMA2(acc[2][0], a23.x, wp.x); FFMA2(acc[2][1], a23.x, wp.y);
            FFMA2(acc[3][0], a23.y, wp.x); FFMA2(acc[3][1], a23.y, wp.y);
            FFMA2(acc[4][0], a45.x, wp.x); FFMA2(acc[4][1], a45.x, wp.y);
            FFMA2(acc[5][0], a45.y, wp.x); FFMA2(acc[5][1], a45.y, wp.y);
            FFMA2(acc[6][0], a67.x, wp.x); FFMA2(acc[6][1], a67.x, wp.y);
            FFMA2(acc[7][0], a67.y, wp.x); FFMA2(acc[7][1], a67.y, wp.y);
        }
        __syncthreads();
    }
    float4 bo = *(const float4*)&b_out[n0 + tx * 4];
#pragma unroll
    for (int i = 0; i < 8; i++) {
        int m = ty * 8 + i;
        F2U p0, p1; p0.u = acc[i][0]; p1.u = acc[i][1];
        float4 o = make_float4(p0.f.x + bo.x, p0.f.y + bo.y,
                               p1.f.x + bo.z, p1.f.y + bo.w);
        *(float4*)&out[(size_t)m * NCLS + n0 + tx * 4] = o;
    }
}

// ---- launch ----
extern "C" void kernel_launch(void* const* d_in, const int* in_sizes, int n_in,
                              void* d_out, int out_size) {
    (void)in_sizes; (void)n_in; (void)out_size;
    const int*   X     = (const int*)d_in[0];
    const float* emb   = (const float*)d_in[1];
    const float* W_ih  = (const float*)d_in[2];
    const float* W_hh  = (const float*)d_in[3];
    const float* b_ih  = (const float*)d_in[4];
    const float* b_hh  = (const float*)d_in[5];
    const float* W_out = (const float*)d_in[6];
    const float* b_out = (const float*)d_in[7];
    float* out = (float*)d_out;

    static bool attr_set = false;
    if (!attr_set) {
        cudaFuncSetAttribute(rnn_kernel, cudaFuncAttributeMaxDynamicSharedMemorySize, RNN_SMEM);
        attr_set = true;
    }

    init_kernel<<<1, 128>>>();
    gates_kernel<<<dim3(HIDD / 64, (S_LEN * B_SZ) / 64), 256>>>(X, emb, W_ih, b_ih, b_hh);
    rnn_kernel<<<RNN_NCTA, 256, RNN_SMEM>>>(W_hh);
    scores_kernel<<<S_LEN - 1, 256>>>();
    softmax_kernel<<<B_SZ, 512>>>();
    attout_kernel<<<dim3(HIDD / 256, B_SZ), 256>>>();
    out_gemm_kernel<<<NCLS / 128, 256>>>(W_out, b_out, out);
}

// round 14
// speedup vs baseline: 1.1077x; 1.1077x over previous
#include <cuda_runtime.h>
#include <cstdint>

#define S_LEN 512
#define B_SZ  64
#define HIDD  1024
#define EMBD  512
#define NCLS  32000
#define FEATD 2048
#define RNN_NCTA 256
#define RNN_KS 16
// hshf [64k][64b] = 16KB ; Wd dup [64k][128] = 32KB  -> 48KB per CTA, 2 CTAs/SM
#define RNN_SMEM (64 * 64 * 4 + 64 * 128 * 4)

#define FFMA2(d, a, b) asm("fma.rn.f32x2 %0, %1, %2, %0;" : "+l"(d) : "l"(a), "l"(b))
union F2U { unsigned long long u; float2 f; };

// ---- device scratch ----
__device__ float g_G[(size_t)S_LEN * B_SZ * HIDD];
__device__ float g_OUT[(size_t)S_LEN * B_SZ * HIDD];
__device__ float g_P[RNN_KS * B_SZ * HIDD];          // 4MB split-K partials
__device__ float g_h0[B_SZ * HIDD];
__device__ float g_scores[(S_LEN - 1) * B_SZ];
__device__ float g_attn[(S_LEN - 1) * B_SZ];
__device__ float g_attout[B_SZ * HIDD];
__device__ unsigned g_bar;                           // monotonic barrier counter

__global__ void init_kernel() {
    int i = blockIdx.x * blockDim.x + threadIdx.x;
    if (i < B_SZ * HIDD) g_h0[i] = 0.f;
    if (i == 0) g_bar = 0u;
}

// ---- K1: gates (two launches over m so rnn lands in the profiled slot) ----
__global__ void __launch_bounds__(256) gates_kernel(const int* __restrict__ X,
                                                    const float* __restrict__ emb,
                                                    const float* __restrict__ W_ih,
                                                    const float* __restrict__ b_ih,
                                                    const float* __restrict__ b_hh,
                                                    int m_base) {
    __shared__ float2 As2[16 * 64];
    __shared__ float  Bs[16 * 68];
    __shared__ int rowidx[64];
    const int n0 = blockIdx.x * 64;
    const int m0 = (m_base + blockIdx.y) * 64;
    const int tid = threadIdx.x;

    if (tid < 64) {
        int m = m0 + tid;
        int t = m >> 6, b = m & 63;
        rowidx[tid] = X[b * S_LEN + t];
    }
    __syncthreads();

    const int tx = tid & 15, ty = tid >> 4;
    unsigned long long acc[4][2];
#pragma unroll
    for (int i = 0; i < 4; i++) { acc[i][0] = 0ull; acc[i][1] = 0ull; }

    const int lm = tid >> 2;
    const int lk = (tid & 3) * 4;

    for (int k0 = 0; k0 < EMBD; k0 += 16) {
        float4 av = *(const float4*)&emb[(size_t)rowidx[lm] * EMBD + k0 + lk];
        As2[(lk + 0) * 64 + lm] = make_float2(av.x, av.x);
        As2[(lk + 1) * 64 + lm] = make_float2(av.y, av.y);
        As2[(lk + 2) * 64 + lm] = make_float2(av.z, av.z);
        As2[(lk + 3) * 64 + lm] = make_float2(av.w, av.w);
        float4 bv = *(const float4*)&W_ih[(size_t)(n0 + lm) * EMBD + k0 + lk];
        Bs[(lk + 0) * 68 + lm] = bv.x; Bs[(lk + 1) * 68 + lm] = bv.y;
        Bs[(lk + 2) * 68 + lm] = bv.z; Bs[(lk + 3) * 68 + lm] = bv.w;
        __syncthreads();
#pragma unroll
        for (int kk = 0; kk < 16; kk++) {
            ulonglong2 a01 = *(const ulonglong2*)&As2[kk * 64 + ty * 4];
            ulonglong2 a23 = *(const ulonglong2*)&As2[kk * 64 + ty * 4 + 2];
            ulonglong2 bp  = *(const ulonglong2*)&Bs[kk * 68 + tx * 4];
            FFMA2(acc[0][0], a01.x, bp.x); FFMA2(acc[0][1], a01.x, bp.y);
            FFMA2(acc[1][0], a01.y, bp.x); FFMA2(acc[1][1], a01.y, bp.y);
            FFMA2(acc[2][0], a23.x, bp.x); FFMA2(acc[2][1], a23.x, bp.y);
            FFMA2(acc[3][0], a23.y, bp.x); FFMA2(acc[3][1], a23.y, bp.y);
        }
        __syncthreads();
    }
    float4 bi = *(const float4*)&b_ih[n0 + tx * 4];
    float4 bh = *(const float4*)&b_hh[n0 + tx * 4];
    float bias[4] = {bi.x + bh.x, bi.y + bh.y, bi.z + bh.z, bi.w + bh.w};
#pragma unroll
    for (int i = 0; i < 4; i++) {
        int m = m0 + ty * 4 + i;
        F2U p0, p1; p0.u = acc[i][0]; p1.u = acc[i][1];
        float4 o = make_float4(p0.f.x + bias[0], p0.f.y + bias[1],
                               p1.f.x + bias[2], p1.f.y + bias[3]);
        *(float4*)&g_G[(size_t)m * HIDD + n0 + tx * 4] = o;
    }
}

// ---- flat barrier: REDG arrive (fire-and-forget) + monotonic counter poll ----
__device__ __forceinline__ void grid_bar(unsigned target) {
    __threadfence();
    __syncthreads();
    if (threadIdx.x == 0) {
        asm volatile("red.release.gpu.global.add.u32 [%0], 1;" :: "l"(&g_bar) : "memory");
        unsigned v;
        do {
            __nanosleep(16);
            asm volatile("ld.volatile.global.u32 %0, [%1];" : "=r"(v) : "l"(&g_bar) : "memory");
        } while (v < target);
        __threadfence();
    }
    __syncthreads();
}

// ---- K2: persistent recurrence — K-split 16, 256 CTAs (2/SM), R6 inner loop ----
// CTA c: jg = c & 15 (64 j-cols), ks = c >> 4 (64 k each).
__global__ void __launch_bounds__(128, 2) rnn_kernel(const float* __restrict__ W_hh) {
    extern __shared__ char smem_raw[];
    float* hshf = (float*)smem_raw;                   // [64k][64b] undup
    float* Wd   = (float*)(smem_raw + 64 * 64 * 4);   // [64k][128] dup: Wd[k][2j]=(w,w)
    const int tid = threadIdx.x;
    const int c = blockIdx.x;
    const int jg = c & 15;   // 64 j-cols per group
    const int ks = c >> 4;   // 64 K each

    // resident W slice, k-major, duplicated
    {
        int jl = tid & 63;
        int kc = (tid >> 6) * 32;
        const float* wr = &W_hh[(size_t)(jg * 64 + jl) * HIDD + ks * 64 + kc];
#pragma unroll
        for (int q = 0; q < 8; q++) {
            float4 wv = *(const float4*)&wr[q * 4];
            *(float2*)&Wd[(kc + q * 4 + 0) * 128 + 2 * jl] = make_float2(wv.x, wv.x);
            *(float2*)&Wd[(kc + q * 4 + 1) * 128 + 2 * jl] = make_float2(wv.y, wv.y);
            *(float2*)&Wd[(kc + q * 4 + 2) * 128 + 2 * jl] = make_float2(wv.z, wv.z);
            *(float2*)&Wd[(kc + q * 4 + 3) * 128 + 2 * jl] = make_float2(wv.w, wv.w);
        }
    }
    __syncthreads();

    const int b0  = (tid & 7) * 8;    // 8 b's per thread
    const int jl0 = (tid >> 3) * 4;   // 4 j's per thread (local)
    const int sb  = tid & 63;         // staging batch
    const int skc = (tid >> 6) * 32;  // staging k-chunk
    unsigned bar = 0;

    for (int t = 0; t < S_LEN; ++t) {
        const float* hprev = (t == 0) ? g_h0 : (g_OUT + (size_t)(t - 1) * B_SZ * HIDD);
        // stage h transposed, undup: hshf[k*64+b] = h[b][k]
        {
            const float* hr = &hprev[(size_t)sb * HIDD + ks * 64 + skc];
#pragma unroll
            for (int q = 0; q < 8; q++) {
                float4 hv = __ldcg((const float4*)&hr[q * 4]);
                hshf[(skc + q * 4 + 0) * 64 + sb] = hv.x;
                hshf[(skc + q * 4 + 1) * 64 + sb] = hv.y;
                hshf[(skc + q * 4 + 2) * 64 + sb] = hv.z;
                hshf[(skc + q * 4 + 3) * 64 + sb] = hv.w;
            }
        }
        __syncthreads();

        unsigned long long acc[4][4];   // acc[j][bpair]
#pragma unroll
        for (int i = 0; i < 4; i++)
#pragma unroll
            for (int p = 0; p < 4; p++) acc[i][p] = 0ull;

#pragma unroll 8
        for (int kk = 0; kk < 64; kk++) {
            ulonglong2 hA = *(const ulonglong2*)&hshf[kk * 64 + b0];      // (b0,b1),(b2,b3)
            ulonglong2 hB = *(const ulonglong2*)&hshf[kk * 64 + b0 + 4];  // (b4,b5),(b6,b7)
            ulonglong2 w01 = *(const ulonglong2*)&Wd[kk * 128 + 2 * jl0];     // dup(j0), dup(j1)
            ulonglong2 w23 = *(const ulonglong2*)&Wd[kk * 128 + 2 * jl0 + 4]; // dup(j2), dup(j3)
            FFMA2(acc[0][0], hA.x, w01.x); FFMA2(acc[0][1], hA.y, w01.x);
            FFMA2(acc[0][2], hB.x, w01.x); FFMA2(acc[0][3], hB.y, w01.x);
            FFMA2(acc[1][0], hA.x, w01.y); FFMA2(acc[1][1], hA.y, w01.y);
            FFMA2(acc[1][2], hB.x, w01.y); FFMA2(acc[1][3], hB.y, w01.y);
            FFMA2(acc[2][0], hA.x, w23.x); FFMA2(acc[2][1], hA.y, w23.x);
            FFMA2(acc[2][2], hB.x, w23.x); FFMA2(acc[2][3], hB.y, w23.x);
            FFMA2(acc[3][0], hA.x, w23.y); FFMA2(acc[3][1], hA.y, w23.y);
            FFMA2(acc[3][2], hB.x, w23.y); FFMA2(acc[3][3], hB.y, w23.y);
        }

        // write partials: g_P[ks][b][jg*64 + jl0 .. +3]
#pragma unroll
        for (int p = 0; p < 4; p++) {
            F2U a0, a1, a2, a3;
            a0.u = acc[0][p]; a1.u = acc[1][p]; a2.u = acc[2][p]; a3.u = acc[3][p];
            float4 lo = make_float4(a0.f.x, a1.f.x, a2.f.x, a3.f.x);
            float4 hi = make_float4(a0.f.y, a1.f.y, a2.f.y, a3.f.y);
            *(float4*)&g_P[ks * (B_SZ * HIDD) + (b0 + 2 * p) * HIDD + jg * 64 + jl0] = lo;
            *(float4*)&g_P[ks * (B_SZ * HIDD) + (b0 + 2 * p + 1) * HIDD + jg * 64 + jl0] = hi;
        }
        bar += RNN_NCTA;
        grid_bar(bar);

        // combine: 256 contiguous elements per CTA (2 per thread), sum 16 partials
        {
            int base = c * 256 + tid * 2;
            float2 s = __ldcg((const float2*)&g_P[base]);
#pragma unroll
            for (int sp = 1; sp < RNN_KS; sp++) {
                float2 p = __ldcg((const float2*)&g_P[sp * (B_SZ * HIDD) + base]);
                s.x += p.x; s.y += p.y;
            }
            float2 g = __ldcg((const float2*)&g_G[(size_t)t * B_SZ * HIDD + base]);
            float2 o = make_float2(tanhf(g.x + s.x), tanhf(g.y + s.y));
            *(float2*)&g_OUT[(size_t)t * B_SZ * HIDD + base] = o;
        }
        bar += RNN_NCTA;
        grid_bar(bar);
    }
}

// ---- K3a: scores ----
__global__ void __launch_bounds__(256) scores_kernel() {
    const int s = blockIdx.x;
    const int w = threadIdx.x >> 5, lane = threadIdx.x & 31;
    const float* Pv = g_OUT + (size_t)s * B_SZ * HIDD;
    const float* Lv = g_OUT + (size_t)(S_LEN - 1) * B_SZ * HIDD;
#pragma unroll
    for (int i = 0; i < 8; i++) {
        int b = w * 8 + i;
        const float* p = Pv + (size_t)b * HIDD;
        const float* l = Lv + (size_t)b * HIDD;
        float acc = 0.f;
#pragma unroll 4
        for (int k = lane; k < HIDD; k += 32) acc += p[k] * l[k];
#pragma unroll
        for (int o = 16; o > 0; o >>= 1) acc += __shfl_down_sync(0xffffffffu, acc, o);
        if (lane == 0) g_scores[s * B_SZ + b] = acc;
    }
}

// ---- K3b: softmax over s per b ----
__global__ void __launch_bounds__(512) softmax_kernel() {
    const int b = blockIdx.x;
    const int tid = threadIdx.x;
    __shared__ float red[512];
    float v = (tid < S_LEN - 1) ? g_scores[tid * B_SZ + b] : -1e30f;
    red[tid] = v;
    __syncthreads();
    for (int s = 256; s > 0; s >>= 1) {
        if (tid < s) red[tid] = fmaxf(red[tid], red[tid + s]);
        __syncthreads();
    }
    float m = red[0];
    __syncthreads();
    float e = (tid < S_LEN - 1) ? expf(v - m) : 0.f;
    red[tid] = e;
    __syncthreads();
    for (int s = 256; s > 0; s >>= 1) {
        if (tid < s) red[tid] += red[tid + s];
        __syncthreads();
    }
    float inv = 1.f / red[0];
    if (tid < S_LEN - 1) g_attn[tid * B_SZ + b] = e * inv;
}

// ---- K3c: att_out ----
__global__ void __launch_bounds__(256) attout_kernel() {
    const int b = blockIdx.y;
    const int h = blockIdx.x * 256 + threadIdx.x;
    float acc = 0.f;
#pragma unroll 4
    for (int s = 0; s < S_LEN - 1; s++)
        acc += g_attn[s * B_SZ + b] * g_OUT[(size_t)s * B_SZ * HIDD + (size_t)b * HIDD + h];
    g_attout[b * HIDD + h] = acc;
}

// ---- K4: out GEMM ----
__global__ void __launch_bounds__(256) out_gemm_kernel(const float* __restrict__ W_out,
                                                       const float* __restrict__ b_out,
                                                       float* __restrict__ out) {
    __shared__ float2 Fs2[16 * 64];
    __shared__ float  Ws[16 * 132];
    const int n0 = blockIdx.x * 128;
    const int tid = threadIdx.x;
    const int tx = tid & 31, ty = tid >> 5;
    const float* last = g_OUT + (size_t)(S_LEN - 1) * B_SZ * HIDD;

    unsigned long long acc[8][2];
#pragma unroll
    for (int i = 0; i < 8; i++) { acc[i][0] = 0ull; acc[i][1] = 0ull; }

    const int mm = tid >> 2;
    const int kq = (tid & 3) * 4;

    for (int k0 = 0; k0 < FEATD; k0 += 16) {
        int k = k0 + kq;
        const float* src = (k < HIDD) ? &g_attout[mm * HIDD + k]
                                      : &last[(size_t)mm * HIDD + (k - HIDD)];
        float4 fv = *(const float4*)src;
        Fs2[(kq + 0) * 64 + mm] = make_float2(fv.x, fv.x);
        Fs2[(kq + 1) * 64 + mm] = make_float2(fv.y, fv.y);
        Fs2[(kq + 2) * 64 + mm] = make_float2(fv.z, fv.z);
        Fs2[(kq + 3) * 64 + mm] = make_float2(fv.w, fv.w);
#pragma unroll
        for (int r = 0; r < 2; r++) {
            int f = tid + r * 256;
            int nn = f >> 2;
            int kq2 = (f & 3) * 4;
            float4 wv = *(const float4*)&W_out[(size_t)(n0 + nn) * FEATD + k0 + kq2];
            Ws[(kq2 + 0) * 132 + nn] = wv.x; Ws[(kq2 + 1) * 132 + nn] = wv.y;
            Ws[(kq2 + 2) * 132 + nn] = wv.z; Ws[(kq2 + 3) * 132 + nn] = wv.w;
        }
        __syncthreads();
#pragma unroll
        for (int kk = 0; kk < 16; kk++) {
            ulonglong2 a01 = *(const ulonglong2*)&Fs2[kk * 64 + ty * 8];
            ulonglong2 a23 = *(const ulonglong2*)&Fs2[kk * 64 + ty * 8 + 2];
            ulonglong2 a45 = *(const ulonglong2*)&Fs2[kk * 64 + ty * 8 + 4];
            ulonglong2 a67 = *(const ulonglong2*)&Fs2[kk * 64 + ty * 8 + 6];
            ulonglong2 wp  = *(const ulonglong2*)&Ws[kk * 132 + tx * 4];
            FFMA2(acc[0][0], a01.x, wp.x); FFMA2(acc[0][1], a01.x, wp.y);
            FFMA2(acc[1][0], a01.y, wp.x); FFMA2(acc[1][1], a01.y, wp.y);
            FFMA2(acc[2][0], a23.x, wp.x); FFMA2(acc[2][1], a23.x, wp.y);
            FFMA2(acc[3][0], a23.y, wp.x); FFMA2(acc[3][1], a23.y, wp.y);
            FFMA2(acc[4][0], a45.x, wp.x); FFMA2(acc[4][1], a45.x, wp.y);
            FFMA2(acc[5][0], a45.y, wp.x); FFMA2(acc[5][1], a45.y, wp.y);
            FFMA2(acc[6][0], a67.x, wp.x); FFMA2(acc[6][1], a67.x, wp.y);
            FFMA2(acc[7][0], a67.y, wp.x); FFMA2(acc[7][1], a67.y, wp.y);
        }
        __syncthreads();
    }
    float4 bo = *(const float4*)&b_out[n0 + tx * 4];
#pragma unroll
    for (int i = 0; i < 8; i++) {
        int m = ty * 8 + i;
        F2U p0, p1; p0.u = acc[i][0]; p1.u = acc[i][1];
        float4 o = make_float4(p0.f.x + bo.x, p0.f.y + bo.y,
                               p1.f.x + bo.z, p1.f.y + bo.w);
        *(float4*)&out[(size_t)m * NCLS + n0 + tx * 4] = o;
    }
}

// ---- launch ----
extern "C" void kernel_launch(void* const* d_in, const int* in_sizes, int n_in,
                              void* d_out, int out_size) {
    (void)in_sizes; (void)n_in; (void)out_size;
    const int*   X     = (const int*)d_in[0];
    const float* emb   = (const float*)d_in[1];
    const float* W_ih  = (const float*)d_in[2];
    const float* W_hh  = (const float*)d_in[3];
    const float* b_ih  = (const float*)d_in[4];
    const float* b_hh  = (const float*)d_in[5];
    const float* W_out = (const float*)d_in[6];
    const float* b_out = (const float*)d_in[7];
    float* out = (float*)d_out;

    static bool attr_set = false;
    if (!attr_set) {
        cudaFuncSetAttribute(rnn_kernel, cudaFuncAttributeMaxDynamicSharedMemorySize, RNN_SMEM);
        attr_set = true;
    }

    init_kernel<<<256, 256>>>();
    gates_kernel<<<dim3(HIDD / 64, 256), 256>>>(X, emb, W_ih, b_ih, b_hh, 0);
    gates_kernel<<<dim3(HIDD / 64, 256), 256>>>(X, emb, W_ih, b_ih, b_hh, 256);
    rnn_kernel<<<RNN_NCTA, 128, RNN_SMEM>>>(W_hh);
    scores_kernel<<<S_LEN - 1, 256>>>();
    softmax_kernel<<<B_SZ, 512>>>();
    attout_kernel<<<dim3(HIDD / 256, B_SZ), 256>>>();
    out_gemm_kernel<<<NCLS / 128, 256>>>(W_out, b_out, out);
}

// round 15
// speedup vs baseline: 1.1932x; 1.0771x over previous
#include <cuda_runtime.h>
#include <cstdint>

#define S_LEN 512
#define B_SZ  64
#define HIDD  1024
#define EMBD  512
#define NCLS  32000
#define FEATD 2048
#define RNN_NCTA 256
#define RNN_KS 16
// hshf [64k][64b] = 16KB ; Wd dup [64k][128] = 32KB  -> 48KB per CTA, 2 CTAs/SM
#define RNN_SMEM (64 * 64 * 4 + 64 * 128 * 4)

#define FFMA2(d, a, b) asm("fma.rn.f32x2 %0, %1, %2, %0;" : "+l"(d) : "l"(a), "l"(b))
union F2U { unsigned long long u; float2 f; };

// ---- device scratch ----
__device__ float g_G[(size_t)S_LEN * B_SZ * HIDD];
__device__ float g_OUT[(size_t)S_LEN * B_SZ * HIDD];
__device__ float g_P[RNN_KS * B_SZ * HIDD];
__device__ float g_h0[B_SZ * HIDD];
__device__ float g_scores[(S_LEN - 1) * B_SZ];
__device__ float g_attn[(S_LEN - 1) * B_SZ];
__device__ float g_attout[B_SZ * HIDD];
__device__ unsigned g_bar;                           // monotonic barrier counter

__global__ void init_kernel() {
    int i = blockIdx.x * blockDim.x + threadIdx.x;
    if (i < B_SZ * HIDD) g_h0[i] = 0.f;
    if (i == 0) g_bar = 0u;
}

// ---- K1: gates (two launches over m so rnn lands in the profiled slot) ----
__global__ void __launch_bounds__(256) gates_kernel(const int* __restrict__ X,
                                                    const float* __restrict__ emb,
                                                    const float* __restrict__ W_ih,
                                                    const float* __restrict__ b_ih,
                                                    const float* __restrict__ b_hh,
                                                    int m_base) {
    __shared__ float2 As2[16 * 64];
    __shared__ float  Bs[16 * 68];
    __shared__ int rowidx[64];
    const int n0 = blockIdx.x * 64;
    const int m0 = (m_base + blockIdx.y) * 64;
    const int tid = threadIdx.x;

    if (tid < 64) {
        int m = m0 + tid;
        int t = m >> 6, b = m & 63;
        rowidx[tid] = X[b * S_LEN + t];
    }
    __syncthreads();

    const int tx = tid & 15, ty = tid >> 4;
    unsigned long long acc[4][2];
#pragma unroll
    for (int i = 0; i < 4; i++) { acc[i][0] = 0ull; acc[i][1] = 0ull; }

    const int lm = tid >> 2;
    const int lk = (tid & 3) * 4;

    for (int k0 = 0; k0 < EMBD; k0 += 16) {
        float4 av = *(const float4*)&emb[(size_t)rowidx[lm] * EMBD + k0 + lk];
        As2[(lk + 0) * 64 + lm] = make_float2(av.x, av.x);
        As2[(lk + 1) * 64 + lm] = make_float2(av.y, av.y);
        As2[(lk + 2) * 64 + lm] = make_float2(av.z, av.z);
        As2[(lk + 3) * 64 + lm] = make_float2(av.w, av.w);
        float4 bv = *(const float4*)&W_ih[(size_t)(n0 + lm) * EMBD + k0 + lk];
        Bs[(lk + 0) * 68 + lm] = bv.x; Bs[(lk + 1) * 68 + lm] = bv.y;
        Bs[(lk + 2) * 68 + lm] = bv.z; Bs[(lk + 3) * 68 + lm] = bv.w;
        __syncthreads();
#pragma unroll
        for (int kk = 0; kk < 16; kk++) {
            ulonglong2 a01 = *(const ulonglong2*)&As2[kk * 64 + ty * 4];
            ulonglong2 a23 = *(const ulonglong2*)&As2[kk * 64 + ty * 4 + 2];
            ulonglong2 bp  = *(const ulonglong2*)&Bs[kk * 68 + tx * 4];
            FFMA2(acc[0][0], a01.x, bp.x); FFMA2(acc[0][1], a01.x, bp.y);
            FFMA2(acc[1][0], a01.y, bp.x); FFMA2(acc[1][1], a01.y, bp.y);
            FFMA2(acc[2][0], a23.x, bp.x); FFMA2(acc[2][1], a23.x, bp.y);
            FFMA2(acc[3][0], a23.y, bp.x); FFMA2(acc[3][1], a23.y, bp.y);
        }
        __syncthreads();
    }
    float4 bi = *(const float4*)&b_ih[n0 + tx * 4];
    float4 bh = *(const float4*)&b_hh[n0 + tx * 4];
    float bias[4] = {bi.x + bh.x, bi.y + bh.y, bi.z + bh.z, bi.w + bh.w};
#pragma unroll
    for (int i = 0; i < 4; i++) {
        int m = m0 + ty * 4 + i;
        F2U p0, p1; p0.u = acc[i][0]; p1.u = acc[i][1];
        float4 o = make_float4(p0.f.x + bias[0], p0.f.y + bias[1],
                               p1.f.x + bias[2], p1.f.y + bias[3]);
        *(float4*)&g_G[(size_t)m * HIDD + n0 + tx * 4] = o;
    }
}

// ---- flat barrier: REDG release arrive + BUSY acquire poll (no nanosleep) ----
__device__ __forceinline__ void grid_bar(unsigned target) {
    __threadfence();
    __syncthreads();
    if (threadIdx.x == 0) {
        asm volatile("red.release.gpu.global.add.u32 [%0], 1;" :: "l"(&g_bar) : "memory");
        unsigned v;
        do {
            asm volatile("ld.acquire.gpu.global.u32 %0, [%1];" : "=r"(v) : "l"(&g_bar) : "memory");
        } while (v < target);
        __threadfence();
    }
    __syncthreads();
}

// ---- K2: persistent recurrence — K-split 16, 256 CTAs (2/SM), 256 thr (4 warps/SMSP) ----
// CTA c: jg = c & 15 (64 j-cols), ks = c >> 4 (64 k each). Tile 4b x 4j per thread.
__global__ void __launch_bounds__(256, 2) rnn_kernel(const float* __restrict__ W_hh) {
    extern __shared__ char smem_raw[];
    float* hshf = (float*)smem_raw;                   // [64k][64b] undup
    float* Wd   = (float*)(smem_raw + 64 * 64 * 4);   // [64k][128] dup: Wd[k][2j]=(w,w)
    const int tid = threadIdx.x;
    const int c = blockIdx.x;
    const int jg = c & 15;   // 64 j-cols per group
    const int ks = c >> 4;   // 64 K each

    // resident W slice, k-major, duplicated (256 threads: 16 k's each)
    {
        int jl = tid & 63;
        int kc = (tid >> 6) * 16;
        const float* wr = &W_hh[(size_t)(jg * 64 + jl) * HIDD + ks * 64 + kc];
#pragma unroll
        for (int q = 0; q < 4; q++) {
            float4 wv = *(const float4*)&wr[q * 4];
            *(float2*)&Wd[(kc + q * 4 + 0) * 128 + 2 * jl] = make_float2(wv.x, wv.x);
            *(float2*)&Wd[(kc + q * 4 + 1) * 128 + 2 * jl] = make_float2(wv.y, wv.y);
            *(float2*)&Wd[(kc + q * 4 + 2) * 128 + 2 * jl] = make_float2(wv.z, wv.z);
            *(float2*)&Wd[(kc + q * 4 + 3) * 128 + 2 * jl] = make_float2(wv.w, wv.w);
        }
    }
    __syncthreads();

    const int b0  = (tid & 15) * 4;   // 4 b's per thread
    const int jl0 = (tid >> 4) * 4;   // 4 j's per thread (local)
    const int sb  = tid & 63;         // staging batch
    const int skc = (tid >> 6) * 16;  // staging k-chunk (16 k's)
    unsigned bar = 0;

    for (int t = 0; t < S_LEN; ++t) {
        const float* hprev = (t == 0) ? g_h0 : (g_OUT + (size_t)(t - 1) * B_SZ * HIDD);
        // stage h transposed, undup: hshf[k*64+b] = h[b][k]
        {
            const float* hr = &hprev[(size_t)sb * HIDD + ks * 64 + skc];
#pragma unroll
            for (int q = 0; q < 4; q++) {
                float4 hv = __ldcg((const float4*)&hr[q * 4]);
                hshf[(skc + q * 4 + 0) * 64 + sb] = hv.x;
                hshf[(skc + q * 4 + 1) * 64 + sb] = hv.y;
                hshf[(skc + q * 4 + 2) * 64 + sb] = hv.z;
                hshf[(skc + q * 4 + 3) * 64 + sb] = hv.w;
            }
        }
        __syncthreads();

        unsigned long long acc[4][2];   // acc[j][bpair]
#pragma unroll
        for (int i = 0; i < 4; i++) { acc[i][0] = 0ull; acc[i][1] = 0ull; }

#pragma unroll 8
        for (int kk = 0; kk < 64; kk++) {
            ulonglong2 hA = *(const ulonglong2*)&hshf[kk * 64 + b0];          // (b0,b1),(b2,b3)
            ulonglong2 w01 = *(const ulonglong2*)&Wd[kk * 128 + 2 * jl0];     // dup(j0), dup(j1)
            ulonglong2 w23 = *(const ulonglong2*)&Wd[kk * 128 + 2 * jl0 + 4]; // dup(j2), dup(j3)
            FFMA2(acc[0][0], hA.x, w01.x); FFMA2(acc[0][1], hA.y, w01.x);
            FFMA2(acc[1][0], hA.x, w01.y); FFMA2(acc[1][1], hA.y, w01.y);
            FFMA2(acc[2][0], hA.x, w23.x); FFMA2(acc[2][1], hA.y, w23.x);
            FFMA2(acc[3][0], hA.x, w23.y); FFMA2(acc[3][1], hA.y, w23.y);
        }

        // write partials: g_P[ks][b][jg*64 + jl0 .. +3]
#pragma unroll
        for (int p = 0; p < 2; p++) {
            F2U a0, a1, a2, a3;
            a0.u = acc[0][p]; a1.u = acc[1][p]; a2.u = acc[2][p]; a3.u = acc[3][p];
            float4 lo = make_float4(a0.f.x, a1.f.x, a2.f.x, a3.f.x);
            float4 hi = make_float4(a0.f.y, a1.f.y, a2.f.y, a3.f.y);
            *(float4*)&g_P[ks * (B_SZ * HIDD) + (b0 + 2 * p) * HIDD + jg * 64 + jl0] = lo;
            *(float4*)&g_P[ks * (B_SZ * HIDD) + (b0 + 2 * p + 1) * HIDD + jg * 64 + jl0] = hi;
        }

        // prefetch G for the combine (G is static; legal before the barrier)
        float gpre = __ldcg(&g_G[(size_t)t * B_SZ * HIDD + c * 256 + tid]);

        bar += RNN_NCTA;
        grid_bar(bar);

        // combine: 1 element per thread, sum 16 partials
        {
            int base = c * 256 + tid;
            float s = __ldcg(&g_P[base]);
#pragma unroll
            for (int sp = 1; sp < RNN_KS; sp++)
                s += __ldcg(&g_P[sp * (B_SZ * HIDD) + base]);
            g_OUT[(size_t)t * B_SZ * HIDD + base] = tanhf(gpre + s);
        }
        bar += RNN_NCTA;
        grid_bar(bar);
    }
}

// ---- K3a: scores ----
__global__ void __launch_bounds__(256) scores_kernel() {
    const int s = blockIdx.x;
    const int w = threadIdx.x >> 5, lane = threadIdx.x & 31;
    const float* Pv = g_OUT + (size_t)s * B_SZ * HIDD;
    const float* Lv = g_OUT + (size_t)(S_LEN - 1) * B_SZ * HIDD;
#pragma unroll
    for (int i = 0; i < 8; i++) {
        int b = w * 8 + i;
        const float* p = Pv + (size_t)b * HIDD;
        const float* l = Lv + (size_t)b * HIDD;
        float acc = 0.f;
#pragma unroll 4
        for (int k = lane; k < HIDD; k += 32) acc += p[k] * l[k];
#pragma unroll
        for (int o = 16; o > 0; o >>= 1) acc += __shfl_down_sync(0xffffffffu, acc, o);
        if (lane == 0) g_scores[s * B_SZ + b] = acc;
    }
}

// ---- K3b: softmax over s per b ----
__global__ void __launch_bounds__(512) softmax_kernel() {
    const int b = blockIdx.x;
    const int tid = threadIdx.x;
    __shared__ float red[512];
    float v = (tid < S_LEN - 1) ? g_scores[tid * B_SZ + b] : -1e30f;
    red[tid] = v;
    __syncthreads();
    for (int s = 256; s > 0; s >>= 1) {
        if (tid < s) red[tid] = fmaxf(red[tid], red[tid + s]);
        __syncthreads();
    }
    float m = red[0];
    __syncthreads();
    float e = (tid < S_LEN - 1) ? expf(v - m) : 0.f;
    red[tid] = e;
    __syncthreads();
    for (int s = 256; s > 0; s >>= 1) {
        if (tid < s) red[tid] += red[tid + s];
        __syncthreads();
    }
    float inv = 1.f / red[0];
    if (tid < S_LEN - 1) g_attn[tid * B_SZ + b] = e * inv;
}

// ---- K3c: att_out ----
__global__ void __launch_bounds__(256) attout_kernel() {
    const int b = blockIdx.y;
    const int h = blockIdx.x * 256 + threadIdx.x;
    float acc = 0.f;
#pragma unroll 4
    for (int s = 0; s < S_LEN - 1; s++)
        acc += g_attn[s * B_SZ + b] * g_OUT[(size_t)s * B_SZ * HIDD + (size_t)b * HIDD + h];
    g_attout[b * HIDD + h] = acc;
}

// ---- K4: out GEMM ----
__global__ void __launch_bounds__(256) out_gemm_kernel(const float* __restrict__ W_out,
                                                       const float* __restrict__ b_out,
                                                       float* __restrict__ out) {
    __shared__ float2 Fs2[16 * 64];
    __shared__ float  Ws[16 * 132];
    const int n0 = blockIdx.x * 128;
    const int tid = threadIdx.x;
    const int tx = tid & 31, ty = tid >> 5;
    const float* last = g_OUT + (size_t)(S_LEN - 1) * B_SZ * HIDD;

    unsigned long long acc[8][2];
#pragma unroll
    for (int i = 0; i < 8; i++) { acc[i][0] = 0ull; acc[i][1] = 0ull; }

    const int mm = tid >> 2;
    const int kq = (tid & 3) * 4;

    for (int k0 = 0; k0 < FEATD; k0 += 16) {
        int k = k0 + kq;
        const float* src = (k < HIDD) ? &g_attout[mm * HIDD + k]
                                      : &last[(size_t)mm * HIDD + (k - HIDD)];
        float4 fv = *(const float4*)src;
        Fs2[(kq + 0) * 64 + mm] = make_float2(fv.x, fv.x);
        Fs2[(kq + 1) * 64 + mm] = make_float2(fv.y, fv.y);
        Fs2[(kq + 2) * 64 + mm] = make_float2(fv.z, fv.z);
        Fs2[(kq + 3) * 64 + mm] = make_float2(fv.w, fv.w);
#pragma unroll
        for (int r = 0; r < 2; r++) {
            int f = tid + r * 256;
            int nn = f >> 2;
            int kq2 = (f & 3) * 4;
            float4 wv = *(const float4*)&W_out[(size_t)(n0 + nn) * FEATD + k0 + kq2];
            Ws[(kq2 + 0) * 132 + nn] = wv.x; Ws[(kq2 + 1) * 132 + nn] = wv.y;
            Ws[(kq2 + 2) * 132 + nn] = wv.z; Ws[(kq2 + 3) * 132 + nn] = wv.w;
        }
        __syncthreads();
#pragma unroll
        for (int kk = 0; kk < 16; kk++) {
            ulonglong2 a01 = *(const ulonglong2*)&Fs2[kk * 64 + ty * 8];
            ulonglong2 a23 = *(const ulonglong2*)&Fs2[kk * 64 + ty * 8 + 2];
            ulonglong2 a45 = *(const ulonglong2*)&Fs2[kk * 64 + ty * 8 + 4];
            ulonglong2 a67 = *(const ulonglong2*)&Fs2[kk * 64 + ty * 8 + 6];
            ulonglong2 wp  = *(const ulonglong2*)&Ws[kk * 132 + tx * 4];
            FFMA2(acc[0][0], a01.x, wp.x); FFMA2(acc[0][1], a01.x, wp.y);
            FFMA2(acc[1][0], a01.y, wp.x); FFMA2(acc[1][1], a01.y, wp.y);
            FFMA2(acc[2][0], a23.x, wp.x); FFMA2(acc[2][1], a23.x, wp.y);
            FFMA2(acc[3][0], a23.y, wp.x); FFMA2(acc[3][1], a23.y, wp.y);
            FFMA2(acc[4][0], a45.x, wp.x); FFMA2(acc[4][1], a45.x, wp.y);
            FFMA2(acc[5][0], a45.y, wp.x); FFMA2(acc[5][1], a45.y, wp.y);
            FFMA2(acc[6][0], a67.x, wp.x); FFMA2(acc[6][1], a67.x, wp.y);
            FFMA2(acc[7][0], a67.y, wp.x); FFMA2(acc[7][1], a67.y, wp.y);
        }
        __syncthreads();
    }
    float4 bo = *(const float4*)&b_out[n0 + tx * 4];
#pragma unroll
    for (int i = 0; i < 8; i++) {
        int m = ty * 8 + i;
        F2U p0, p1; p0.u = acc[i][0]; p1.u = acc[i][1];
        float4 o = make_float4(p0.f.x + bo.x, p0.f.y + bo.y,
                               p1.f.x + bo.z, p1.f.y + bo.w);
        *(float4*)&out[(size_t)m * NCLS + n0 + tx * 4] = o;
    }
}

// ---- launch ----
extern "C" void kernel_launch(void* const* d_in, const int* in_sizes, int n_in,
                              void* d_out, int out_size) {
    (void)in_sizes; (void)n_in; (void)out_size;
    const int*   X     = (const int*)d_in[0];
    const float* emb   = (const float*)d_in[1];
    const float* W_ih  = (const float*)d_in[2];
    const float* W_hh  = (const float*)d_in[3];
    const float* b_ih  = (const float*)d_in[4];
    const float* b_hh  = (const float*)d_in[5];
    const float* W_out = (const float*)d_in[6];
    const float* b_out = (const float*)d_in[7];
    float* out = (float*)d_out;

    static bool attr_set = false;
    if (!attr_set) {
        cudaFuncSetAttribute(rnn_kernel, cudaFuncAttributeMaxDynamicSharedMemorySize, RNN_SMEM);
        attr_set = true;
    }

    init_kernel<<<256, 256>>>();
    gates_kernel<<<dim3(HIDD / 64, 256), 256>>>(X, emb, W_ih, b_ih, b_hh, 0);
    gates_kernel<<<dim3(HIDD / 64, 256), 256>>>(X, emb, W_ih, b_ih, b_hh, 256);
    rnn_kernel<<<RNN_NCTA, 256, RNN_SMEM>>>(W_hh);
    scores_kernel<<<S_LEN - 1, 256>>>();
    softmax_kernel<<<B_SZ, 512>>>();
    attout_kernel<<<dim3(HIDD / 256, B_SZ), 256>>>();
    out_gemm_kernel<<<NCLS / 128, 256>>>(W_out, b_out, out);
}